// round 4
// baseline (speedup 1.0000x reference)
#include <cuda_runtime.h>

#define DIM 4096
#define NQ 12
#define DEPTH 4

// Composed CNOT-ring permutation (gather form): out_i = x_i ^ x_{i+1} for i=0..9,
// out10 = x10^x11^x0, out11 = x11^x0.  (verified in round 1/2)
__host__ __device__ __forceinline__ constexpr int sig(int x) {
    int r = (x ^ (x >> 1)) & 0x3FF;
    r |= (((x >> 10) ^ (x >> 11) ^ x) & 1) << 10;
    r |= (((x >> 11) ^ x) & 1) << 11;
    return r;
}
// Placement P (inter-layer buffer S0): bank-bit folds b0^=y5^y7, b1^=y6, b2^=y7, b3^=y8.
// Full-rank (conflict-free) for: pass-B store / layer-0 init (lanes vary y4..y8),
// pass-A load with sigma (directions e2+e3, e3+e4, e4+e0, e0+e1, e0+e1+e2),
// readout load with sigma (directions e0, e0+e1, e1+e2, e2+e3, e3+e4).
__host__ __device__ __forceinline__ constexpr int PP(int y) {
    return y ^ ((y >> 5) & 1) ^ (((y >> 6) & 1) << 1) ^ (((y >> 7) & 1) * 5)
             ^ (((y >> 8) & 1) << 3);
}
// Placement Q (intra-layer buffer S1): b0^=y5, b1^=y6, b2^=y7, b3^=y8.
// Full-rank for pass-A store (lanes vary y3..y7) and pass-B load (lanes vary y4..y8).
__host__ __device__ __forceinline__ constexpr int QQ(int y) {
    return y ^ ((y >> 5) & 1) ^ (((y >> 6) & 1) << 1) ^ (((y >> 7) & 1) << 2)
             ^ (((y >> 8) & 1) << 3);
}

__global__ __launch_bounds__(512, 1)
void qsim_kernel(const float* __restrict__ x, const float* __restrict__ theta,
                 const float* __restrict__ w, const float* __restrict__ b,
                 float* __restrict__ out) {
    __shared__ float S0[DIM];   // inter-layer buffer (PP placement)
    __shared__ float S1[DIM];   // intra-layer buffer (QQ placement)
    __shared__ float CS[DEPTH * NQ];
    __shared__ float SN[DEPTH * NQ];
    __shared__ float red[32];

    const int tid = threadIdx.x;
    const int lane = tid & 31;
    const int wid = tid >> 5;   // 0..15

    // half-angle cos/sin: angle[d][q] = theta[d][q] + 0.1*x[q]
    if (tid < DEPTH * NQ) {
        const int q = tid % NQ;
        const float a = 0.5f * (theta[tid] + 0.1f * x[q]);
        float s, c;
        __sincosf(a, &s, &c);
        CS[tid] = c;
        SN[tid] = s;
    }
    __syncthreads();

    // Layout A: i = wid<<8 | lane<<3 | k     (k bits0-2, lane bits3-7, wid bits8-11)
    // Layout B: i = k<<9 | (lane&1)<<8 | (lane>>1)<<4 | wid
    //           (wid bits0-3, lane1-4 bits4-7, lane0 bit8, k bits9-11)
    const int baseA = (wid << 8) | (lane << 3);
    const int baseB = ((lane & 1) << 8) | ((lane >> 1) << 4) | wid;
    const int ldA = PP(sig(baseA));   // ^ PP(sig(k))      [A gather, prev ring fused]
    const int stA = QQ(baseA);        // ^ k               [A scatter]
    const int ldB = QQ(baseB);        // ^ (k<<9)          [B gather]
    const int stB = PP(baseB);        // ^ (k<<9)          [B scatter]

    float v[8];

    // ================= Layer 0: product state (all 12 RYs on e0) ============
    // index bit bp -> qubit 11-bp; amp = prod (bit ? sin : cos)
    {
        float P = 1.f;
#pragma unroll
        for (int bp = 0; bp < 9; ++bp)
            P *= ((baseB >> bp) & 1) ? SN[11 - bp] : CS[11 - bp];
#pragma unroll
        for (int k = 0; k < 8; ++k) {
            const float a = P * ((k & 1) ? SN[2] : CS[2])
                              * ((k & 2) ? SN[1] : CS[1])
                              * ((k & 4) ? SN[0] : CS[0]);
            S0[stB ^ (k << 9)] = a;
        }
    }
    __syncthreads();

    // ================= Layers 1..3 ================
#pragma unroll
    for (int d = 1; d < DEPTH; ++d) {
        const float* C = CS + d * NQ;
        const float* Sn = SN + d * NQ;

        // ---- Pass A: gather (prev CNOT ring fused), rotate qubits 11,10,9 (reg)
        //      and 8..4 (shfl), scatter to S1
#pragma unroll
        for (int k = 0; k < 8; ++k) v[k] = S0[ldA ^ PP(sig(k))];

#pragma unroll
        for (int rb = 0; rb < 3; ++rb) {          // index bit rb -> qubit 11-rb
            const int m = 1 << rb;
            const float c = C[11 - rb], s = Sn[11 - rb];
#pragma unroll
            for (int k = 0; k < 8; ++k)
                if (!(k & m)) {
                    const float lo = v[k], hi = v[k | m];
                    v[k]     = c * lo - s * hi;
                    v[k | m] = s * lo + c * hi;
                }
        }
#pragma unroll
        for (int bs = 0; bs < 5; ++bs) {          // lane bit bs -> qubit 8-bs
            const int m = 1 << bs;
            const float c = C[8 - bs], s = Sn[8 - bs];
            const float se = (lane & m) ? s : -s;
#pragma unroll
            for (int k = 0; k < 8; ++k) {
                const float o = __shfl_xor_sync(0xffffffffu, v[k], m);
                v[k] = c * v[k] + se * o;
            }
        }
#pragma unroll
        for (int k = 0; k < 8; ++k) S1[stA ^ k] = v[k];
        __syncthreads();

        // ---- Pass B: gather from S1, rotate qubit 3 (shfl on lane bit0),
        //      qubits 2,1,0 (reg on k bits), scatter to S0
#pragma unroll
        for (int k = 0; k < 8; ++k) v[k] = S1[ldB ^ (k << 9)];

        {
            const float c = C[3], s = Sn[3];
            const float se = (lane & 1) ? s : -s;
#pragma unroll
            for (int k = 0; k < 8; ++k) {
                const float o = __shfl_xor_sync(0xffffffffu, v[k], 1);
                v[k] = c * v[k] + se * o;
            }
        }
#pragma unroll
        for (int rb = 0; rb < 3; ++rb) {          // k bit rb -> index bit 9+rb -> qubit 2-rb
            const int m = 1 << rb;
            const float c = C[2 - rb], s = Sn[2 - rb];
#pragma unroll
            for (int k = 0; k < 8; ++k)
                if (!(k & m)) {
                    const float lo = v[k], hi = v[k | m];
                    v[k]     = c * lo - s * hi;
                    v[k | m] = s * lo + c * hi;
                }
        }
#pragma unroll
        for (int k = 0; k < 8; ++k) S0[stB ^ (k << 9)] = v[k];
        __syncthreads();
    }

    // ================= Readout (final CNOT ring fused) ================
    // Readout layout: r = wid<<8 | k<<5 | lane  (coalesced global access)
    const int baseR = (wid << 8) | lane;
    const int ldR = PP(sig(baseR));
    float a0 = 0.f, a1 = 0.f;
#pragma unroll
    for (int k = 0; k < 8; ++k) {
        const int r = baseR | (k << 5);
        const float vv = S0[ldR ^ PP(sig(k << 5))];
        out[2 + r] = vv;
        const float p = vv * vv;
        a0 += p * w[r];
        a1 += p * w[DIM + r];
    }
#pragma unroll
    for (int o = 16; o > 0; o >>= 1) {
        a0 += __shfl_down_sync(0xffffffffu, a0, o);
        a1 += __shfl_down_sync(0xffffffffu, a1, o);
    }
    if (lane == 0) { red[wid] = a0; red[16 + wid] = a1; }
    __syncthreads();
    if (wid == 0) {
        float r0 = (lane < 16) ? red[lane] : 0.f;
        float r1 = (lane < 16) ? red[16 + lane] : 0.f;
#pragma unroll
        for (int o = 8; o > 0; o >>= 1) {
            r0 += __shfl_down_sync(0xffffffffu, r0, o);
            r1 += __shfl_down_sync(0xffffffffu, r1, o);
        }
        if (lane == 0) {
            out[0] = r0 + b[0];
            out[1] = r1 + b[1];
        }
    }
}

extern "C" void kernel_launch(void* const* d_in, const int* in_sizes, int n_in,
                              void* d_out, int out_size) {
    const float* x = nullptr;
    const float* th = nullptr;
    const float* w = nullptr;
    const float* b = nullptr;
    for (int i = 0; i < n_in; ++i) {
        const int s = in_sizes[i];
        if (s == NQ) x = (const float*)d_in[i];
        else if (s == DEPTH * NQ) th = (const float*)d_in[i];
        else if (s == 2 * DIM) w = (const float*)d_in[i];
        else if (s == 2) b = (const float*)d_in[i];
    }
    qsim_kernel<<<1, 512>>>(x, th, w, b, (float*)d_out);
}